// round 6
// baseline (speedup 1.0000x reference)
#include <cuda_runtime.h>
#include <cuda_fp16.h>
#include <stdint.h>

// MultiLevelSparseHashEncoding — round 6.
// vs round 5 (118.9us; main ~90us latency-bound at 48% occ): ONE level per
// block -> 65.5KB table -> 3 CTAs x 512 thr per SM (48 warps, 75% occ).
// Stores stay coalesced (4B half2 bits into stage[level][point]); out
// transpose reads 16 planes.  __launch_bounds__(512,3) caps regs at 42.

#define NLVL 16
#define NENC 16384
#define NPTS (1 << 20)
#define TPB  512
#define PPB  8192
#define GPT  (PPB / TPB)            // 16 points per thread
#define SMEM_BYTES ((NENC + 1) * (int)sizeof(__half2))   // 65540
#define SCALE    4096.0f
#define INV_SCALE (1.0f / 4096.0f)

__constant__ int c_res[NLVL] = {16, 20, 25, 32, 40, 50, 64, 80,
                                101, 128, 161, 203, 256, 322, 406, 512};
__constant__ int c_nle[NLVL] = {4096, 8000, 15625, 16384, 16384, 16384,
                                16384, 16384, 16384, 16384, 16384, 16384,
                                16384, 16384, 16384, 16384};

__device__ float    g_xs[3u * NPTS];                 // SoA coords (12 MB)
__device__ unsigned g_stage[(size_t)NLVL * NPTS];    // [level][point] half2 bits (64 MB)

// ---------------------------------------------------------------- pre-kernel
__global__ __launch_bounds__(1024)
void transpose_x_kernel(const float* __restrict__ x)
{
    const int p = blockIdx.x * 1024 + threadIdx.x;
    const float a = x[3 * p + 0];
    const float b = x[3 * p + 1];
    const float c = x[3 * p + 2];
    g_xs[p]             = a;
    g_xs[NPTS + p]      = b;
    g_xs[2u * NPTS + p] = c;
}

// ---------------------------------------------------------------- per-level
// returns the fp16 accumulator still scaled by 2^12
template <bool DIRECT>
__device__ __forceinline__ __half2
level_feat(const __half2* __restrict__ tab, const int R,
           const float xv0, const float xv1, const float xv2)
{
    const float halfR = 0.5f * (float)R;
    const float t0 = __fadd_rn(__fmul_rn(__fadd_rn(xv0, 1.0f), halfR), -0.5f);
    const float t1 = __fadd_rn(__fmul_rn(__fadd_rn(xv1, 1.0f), halfR), -0.5f);
    const float t2 = __fadd_rn(__fmul_rn(__fadd_rn(xv2, 1.0f), halfR), -0.5f);

    const float fl0 = floorf(t0), fl1 = floorf(t1), fl2 = floorf(t2);
    const float fr0 = t0 - fl0, fr1 = t1 - fl1, fr2 = t2 - fl2;
    const int   i0  = (int)fl0, i1 = (int)fl1, i2 = (int)fl2;

    // validity folded into per-dim weights: invalid corner -> weight 0
    const float wx0 = i0     >= 0 ? 1.0f - fr0 : 0.0f;
    const float wx1 = i0 + 1 <  R ? fr0        : 0.0f;
    const float wy0 = i1     >= 0 ? 1.0f - fr1 : 0.0f;
    const float wy1 = i1 + 1 <  R ? fr1        : 0.0f;
    const float wz[2] = {i2     >= 0 ? 1.0f - fr2 : 0.0f,
                         i2 + 1 <  R ? fr2        : 0.0f};
    const float wxy[4] = {wx0 * wy0, wx0 * wy1, wx1 * wy0, wx1 * wy1};

    unsigned kx[2], kyz[4];
    if (DIRECT) {
        const int R2 = R * R;
        const int a0 = max(i0, 0), a1 = min(i0 + 1, R - 1);
        const int b0 = max(i1, 0), b1 = min(i1 + 1, R - 1);
        const int d0 = max(i2, 0), d1 = min(i2 + 1, R - 1);
        kx[0] = (unsigned)(a0 * R2); kx[1] = (unsigned)(a1 * R2);
        kyz[0] = (unsigned)(b0 * R + d0); kyz[1] = (unsigned)(b0 * R + d1);
        kyz[2] = (unsigned)(b1 * R + d0); kyz[3] = (unsigned)(b1 * R + d1);
    } else {
        kx[0] = (unsigned)i0; kx[1] = (unsigned)(i0 + 1);
        const unsigned hy0 = (unsigned)i1 * 2654435761u;
        const unsigned hy1 = (unsigned)(i1 + 1) * 2654435761u;
        const unsigned hz0 = (unsigned)i2 * 805459861u;
        const unsigned hz1 = (unsigned)(i2 + 1) * 805459861u;
        kyz[0] = hy0 ^ hz0; kyz[1] = hy0 ^ hz1;
        kyz[2] = hy1 ^ hz0; kyz[3] = hy1 ^ hz1;
    }
    const unsigned mask = NENC - 1;

    __half2 acc = __float2half2_rn(0.0f);
    #pragma unroll
    for (int c = 0; c < 8; ++c) {
        const int ox = (c >> 2) & 1, oyz = c & 3;
        unsigned id;
        if (DIRECT) id = kx[ox] + kyz[oyz];
        else        id = (kx[ox] ^ kyz[oyz]) & mask;   // single LOP3
        const float   w  = wxy[2 * ox + (oyz >> 1)] * wz[oyz & 1];
        const __half2 w2 = __float2half2_rn(w);
        acc = __hfma2(w2, tab[id], acc);
    }
    return acc;
}

// ---------------------------------------------------------------- main
__global__ __launch_bounds__(TPB, 3)
void hashgrid_level_kernel(const float* __restrict__ emb)
{
    extern __shared__ __half2 tab[];

    const int l     = blockIdx.x & (NLVL - 1);    // level = fastest grid dim
    const int chunk = blockIdx.x >> 4;
    const int R  = c_res[l];
    const int ne = c_nle[l];

    const float2* __restrict__ src =
        reinterpret_cast<const float2*>(emb) + (size_t)l * (NENC + 1);
    for (int i = threadIdx.x; i <= ne; i += TPB) {
        const float2 v = src[i];
        tab[i] = __floats2half2_rn(v.x * SCALE, v.y * SCALE);
    }
    __syncthreads();

    unsigned* __restrict__ stage = g_stage + (size_t)l * NPTS;

    int p = chunk * PPB + threadIdx.x;
    #pragma unroll 1
    for (int g = 0; g < GPT; ++g, p += TPB) {
        const float xv0 = g_xs[p];
        const float xv1 = g_xs[NPTS + p];
        const float xv2 = g_xs[2u * NPTS + p];

        __half2 r;
        if (l < 3) r = level_feat<true >(tab, R, xv0, xv1, xv2);
        else       r = level_feat<false>(tab, R, xv0, xv1, xv2);

        stage[p] = *reinterpret_cast<unsigned*>(&r);   // coalesced 4 B store
    }
}

// ---------------------------------------------------------------- transpose
#define TPB3 256
__global__ __launch_bounds__(TPB3)
void transpose_out_kernel(float4* __restrict__ out)
{
    __shared__ unsigned arr[NLVL][TPB3 + 1];      // pitch 257 -> low conflicts

    const int base = blockIdx.x * TPB3;
    const int tid  = threadIdx.x;

    #pragma unroll
    for (int m = 0; m < NLVL; ++m)
        arr[m][tid] = g_stage[(size_t)m * NPTS + base + tid];
    __syncthreads();

    // each point emits 8 float4 (16 levels x 2 floats); fully coalesced out
    #pragma unroll
    for (int k = 0; k < 8; ++k) {
        const int local = k * TPB3 + tid;         // float4 index within block
        const int p_off = local >> 3;
        const int j     = local & 7;              // level pair
        const unsigned a = arr[2 * j][p_off];
        const unsigned b = arr[2 * j + 1][p_off];
        const float2 fa = __half22float2(*reinterpret_cast<const __half2*>(&a));
        const float2 fb = __half22float2(*reinterpret_cast<const __half2*>(&b));
        out[(size_t)base * 8 + local] =
            make_float4(fa.x * INV_SCALE, fa.y * INV_SCALE,
                        fb.x * INV_SCALE, fb.y * INV_SCALE);
    }
}

// ---------------------------------------------------------------- launch
extern "C" void kernel_launch(void* const* d_in, const int* in_sizes, int n_in,
                              void* d_out, int out_size)
{
    (void)n_in; (void)out_size;
    const float* x;
    const float* emb;
    if (in_sizes[0] == 3 * NPTS) { x = (const float*)d_in[0]; emb = (const float*)d_in[1]; }
    else                         { x = (const float*)d_in[1]; emb = (const float*)d_in[0]; }
    float4* out = (float4*)d_out;

    cudaFuncSetAttribute(hashgrid_level_kernel,
                         cudaFuncAttributeMaxDynamicSharedMemorySize, SMEM_BYTES);

    transpose_x_kernel<<<NPTS / 1024, 1024>>>(x);

    const int blocks = (NPTS / PPB) * NLVL;       // 128 chunks * 16 = 2048
    hashgrid_level_kernel<<<blocks, TPB, SMEM_BYTES>>>(emb);

    transpose_out_kernel<<<NPTS / TPB3, TPB3>>>(out);
}